// round 2
// baseline (speedup 1.0000x reference)
#include <cuda_runtime.h>

#define NROWS 2000000
#define D 128
#define NSEG 4096

// ---- scratch (no allocations allowed) ----
__device__ float    g_s[NROWS];
__device__ float    g_segsum[NSEG];
__device__ unsigned g_segmaxb[NSEG];
__device__ int      g_is64;

// ---- batch_idx may be int32 (JAX x64 disabled) or int64; detect at runtime ----
__device__ __forceinline__ int seg_at(const void* p, int is64, long long i) {
    int v = is64 ? (int)((const long long*)p)[i] : ((const int*)p)[i];
    // defensive clamp: wrong dtype guess shows up as rel_err, not a crash
    return min(max(v, 0), NSEG - 1);
}

// monotone order-preserving float<->uint mapping for atomicMax
__device__ __forceinline__ unsigned fmap(float f) {
    unsigned u = __float_as_uint(f);
    return (u & 0x80000000u) ? ~u : (u | 0x80000000u);
}
__device__ __forceinline__ float funmap(unsigned m) {
    return (m & 0x80000000u) ? __uint_as_float(m ^ 0x80000000u)
                             : __uint_as_float(~m);
}
__device__ __forceinline__ float tanh_fast(float v) {
    float e = __expf(2.0f * v);
    return 1.0f - __fdividef(2.0f, e + 1.0f);
}

// ---------------------------------------------------------------------------
// k0: zero out-region + seg scratch; thread 0 detects batch_idx dtype.
// Reading slot N/4 and N/8 as int64 is in-bounds for both dtypes
// (int32 buffer holds N/2 int64 slots). True int64 -> values in [0,NSEG);
// int32-as-int64 -> high word = mid-array segment (~1024..2047, nonzero)
// so the value is >= 2^32.
// ---------------------------------------------------------------------------
__global__ void k0_init(float* __restrict__ out, const void* __restrict__ idxp) {
    long long i = (long long)blockIdx.x * blockDim.x + threadIdx.x;
    if (i < NSEG * D) out[i] = 0.0f;
    if (i < NSEG) { g_segsum[i] = 0.0f; g_segmaxb[i] = 0u; }
    if (i == 0) {
        const long long* p64 = (const long long*)idxp;
        long long a = p64[NROWS / 4];
        long long b = p64[NROWS / 8];
        g_is64 = (a >= 0 && a < NSEG && b >= 0 && b < NSEG) ? 1 : 0;
    }
}

// ---------------------------------------------------------------------------
// k1: per-row MLP score. Block tile = 128 rows x 128 hidden, K=128.
// 256 threads, 8x8 register micro-tile. Fused bias+tanh+W2 dot, block
// reduction, then segmented max with one atomicMax per segment run.
// ---------------------------------------------------------------------------
__global__ __launch_bounds__(256, 2) void k1_mlp(
    const float* __restrict__ x, const float* __restrict__ W1,
    const float* __restrict__ b1, const float* __restrict__ W2,
    const float* __restrict__ b2, const void* __restrict__ idxp)
{
    __shared__ float xs[16][128];
    __shared__ float ws[16][128];
    __shared__ float red[16][129];
    __shared__ float s_val[128];
    __shared__ int   s_seg[128];

    const int tid = threadIdx.x;
    const int tx = tid & 15;
    const int ty = tid >> 4;
    const size_t row0 = (size_t)blockIdx.x * 128;
    const int is64 = g_is64;

    float acc[8][8];
#pragma unroll
    for (int i = 0; i < 8; i++)
#pragma unroll
        for (int j = 0; j < 8; j++) acc[i][j] = 0.0f;

    for (int k0 = 0; k0 < 128; k0 += 16) {
        {   // x tile transposed: 128 rows x 16 k
            int lr = tid >> 1;
            int lk = (tid & 1) * 8;
            const float4* xp =
                reinterpret_cast<const float4*>(x + (row0 + lr) * D + k0 + lk);
            float4 v0 = xp[0];
            float4 v1 = xp[1];
            xs[lk + 0][lr] = v0.x; xs[lk + 1][lr] = v0.y;
            xs[lk + 2][lr] = v0.z; xs[lk + 3][lr] = v0.w;
            xs[lk + 4][lr] = v1.x; xs[lk + 5][lr] = v1.y;
            xs[lk + 6][lr] = v1.z; xs[lk + 7][lr] = v1.w;
        }
        {   // W1 chunk: 16 k-rows x 128 cols (native layout)
            int kk = tid >> 4;
            int c  = (tid & 15) * 8;
            const float4* wp =
                reinterpret_cast<const float4*>(W1 + (size_t)(k0 + kk) * D + c);
            *reinterpret_cast<float4*>(&ws[kk][c])     = wp[0];
            *reinterpret_cast<float4*>(&ws[kk][c + 4]) = wp[1];
        }
        __syncthreads();
#pragma unroll
        for (int k = 0; k < 16; k++) {
            float a[8], b[8];
            *reinterpret_cast<float4*>(&a[0]) = *reinterpret_cast<const float4*>(&xs[k][ty * 8]);
            *reinterpret_cast<float4*>(&a[4]) = *reinterpret_cast<const float4*>(&xs[k][ty * 8 + 4]);
            *reinterpret_cast<float4*>(&b[0]) = *reinterpret_cast<const float4*>(&ws[k][tx * 8]);
            *reinterpret_cast<float4*>(&b[4]) = *reinterpret_cast<const float4*>(&ws[k][tx * 8 + 4]);
#pragma unroll
            for (int i = 0; i < 8; i++)
#pragma unroll
                for (int j = 0; j < 8; j++)
                    acc[i][j] = fmaf(a[i], b[j], acc[i][j]);
        }
        __syncthreads();
    }

    // epilogue: bias + tanh + dot with W2 over this thread's 8 cols
    float b1v[8], w2v[8];
#pragma unroll
    for (int j = 0; j < 8; j++) {
        b1v[j] = b1[tx * 8 + j];
        w2v[j] = W2[tx * 8 + j];
    }
#pragma unroll
    for (int i = 0; i < 8; i++) {
        float t = 0.0f;
#pragma unroll
        for (int j = 0; j < 8; j++) {
            float h = tanh_fast(acc[i][j] + b1v[j]);
            t = fmaf(h, w2v[j], t);
        }
        red[tx][ty * 8 + i] = t;
    }
    __syncthreads();

    if (tid < 128) {
        float t = 0.0f;
#pragma unroll
        for (int g = 0; g < 16; g++) t += red[g][tid];
        float sv = t + b2[0];
        g_s[row0 + tid] = sv;
        s_val[tid] = sv;
        s_seg[tid] = seg_at(idxp, is64, row0 + tid);
    }
    __syncthreads();

    // segmented max: rows sorted by seg -> one atomic per run
    if (tid < 128) {
        int seg = s_seg[tid];
        if (tid == 0 || s_seg[tid - 1] != seg) {
            float m = s_val[tid];
            int j = tid + 1;
            while (j < 128 && s_seg[j] == seg) { m = fmaxf(m, s_val[j]); j++; }
            atomicMax(&g_segmaxb[seg], fmap(m));
        }
    }
}

// ---------------------------------------------------------------------------
// k2: e = exp(s - seg_max[idx]); store e into the alpha slot of d_out;
// shared-memory bucket aggregation of seg_sum (sorted idx -> tiny range).
// ---------------------------------------------------------------------------
__global__ __launch_bounds__(256) void k2_exp(
    const void* __restrict__ idxp, float* __restrict__ e_out)
{
    __shared__ float buck[1024];
    const int tid = threadIdx.x;
    const long long base = (long long)blockIdx.x * 1024;
    const long long last = min(base + 1023LL, (long long)NROWS - 1);
    const int is64 = g_is64;
    const int seg_lo = seg_at(idxp, is64, base);
    const int seg_hi = seg_at(idxp, is64, last);
    const int range = seg_hi - seg_lo + 1;
    const bool use_smem = (range > 0 && range <= 1024);
    if (use_smem)
        for (int k = tid; k < range; k += 256) buck[k] = 0.0f;
    __syncthreads();

    for (int j = tid; j < 1024; j += 256) {
        long long r = base + j;
        if (r >= NROWS) break;
        int seg = seg_at(idxp, is64, r);
        float smax = funmap(g_segmaxb[seg]);
        float e = __expf(g_s[r] - smax);
        e_out[r] = e;
        if (use_smem) atomicAdd(&buck[seg - seg_lo], e);
        else          atomicAdd(&g_segsum[seg], e);
    }
    __syncthreads();

    if (use_smem)
        for (int k = tid; k < range; k += 256) {
            float v = buck[k];
            if (v != 0.0f) atomicAdd(&g_segsum[seg_lo + k], v);
        }
}

// ---------------------------------------------------------------------------
// k3: alpha = e/(seg_sum+1e-16) (in-place over e), and out += x*alpha with
// register accumulation per segment run (128 threads = one dim each).
// ---------------------------------------------------------------------------
__global__ __launch_bounds__(128) void k3_agg(
    const float* __restrict__ x, const void* __restrict__ idxp,
    float* __restrict__ alpha, float* __restrict__ out)
{
    __shared__ float sa[512];
    __shared__ int   sseg[512];
    const int tid = threadIdx.x;
    const long long base = (long long)blockIdx.x * 512;
    const int nrows = (int)min(512LL, (long long)NROWS - base);
    const int is64 = g_is64;

    for (int j = tid; j < nrows; j += 128) {
        int seg = seg_at(idxp, is64, base + j);
        float e = alpha[base + j];
        float a = __fdividef(e, g_segsum[seg] + 1e-16f);
        sa[j] = a;
        sseg[j] = seg;
        alpha[base + j] = a;   // final alpha output
    }
    __syncthreads();

    float acc = 0.0f;
    int cur = sseg[0];
    for (int j = 0; j < nrows; j++) {
        int sg = sseg[j];
        if (sg != cur) {
            atomicAdd(&out[(size_t)cur * D + tid], acc);
            acc = 0.0f;
            cur = sg;
        }
        acc = fmaf(x[(size_t)(base + j) * D + tid], sa[j], acc);
    }
    atomicAdd(&out[(size_t)cur * D + tid], acc);
}

// ---------------------------------------------------------------------------
extern "C" void kernel_launch(void* const* d_in, const int* in_sizes, int n_in,
                              void* d_out, int out_size)
{
    const float* x  = (const float*)d_in[0];
    const float* W1 = (const float*)d_in[1];
    const float* b1 = (const float*)d_in[2];
    const float* W2 = (const float*)d_in[3];
    const float* b2 = (const float*)d_in[4];
    const void*  idxp = d_in[5];

    float* outp  = (float*)d_out;          // (4096, 128)
    float* alpha = outp + NSEG * D;        // (N, 1)  -- holds e between k2/k3

    k0_init<<<(NSEG * D + 255) / 256, 256>>>(outp, idxp);
    k1_mlp <<<NROWS / 128, 256>>>(x, W1, b1, W2, b2, idxp);
    k2_exp <<<(NROWS + 1023) / 1024, 256>>>(idxp, alpha);
    k3_agg <<<(NROWS + 511) / 512, 128>>>(x, idxp, alpha, outp);
}

// round 3
// speedup vs baseline: 1.3635x; 1.3635x over previous
#include <cuda_runtime.h>

#define NROWS 2000000
#define D 128
#define NSEG 4096
#define WPAD 132          // ws row stride (words): (4*tig+gid)%32 conflict-free
#define XPAD 68           // xs row stride (words): 68%32=4 -> ldmatrix conflict-free
#define K1_SMEM_BYTES ((128*WPAD + 2*128*XPAD + 3*128) * 4)

// ---- scratch (no allocations allowed) ----
__device__ float    g_s[NROWS];
__device__ float    g_segsum[NSEG];
__device__ unsigned g_segmaxb[NSEG];
__device__ int      g_is64;
__device__ float    g_w1r[D * D];   // W1 pre-rounded to tf32 (RNA)

// ---- batch_idx may be int32 or int64; detect at runtime ----
__device__ __forceinline__ int seg_at(const void* p, int is64, long long i) {
    int v = is64 ? (int)((const long long*)p)[i] : ((const int*)p)[i];
    return min(max(v, 0), NSEG - 1);
}

__device__ __forceinline__ unsigned fmap(float f) {
    unsigned u = __float_as_uint(f);
    return (u & 0x80000000u) ? ~u : (u | 0x80000000u);
}
__device__ __forceinline__ float funmap(unsigned m) {
    return (m & 0x80000000u) ? __uint_as_float(m ^ 0x80000000u)
                             : __uint_as_float(~m);
}
__device__ __forceinline__ float tanh_fast(float v) {
    float e = __expf(2.0f * v);
    return 1.0f - __fdividef(2.0f, e + 1.0f);
}
__device__ __forceinline__ unsigned f2tf(float f) {
    unsigned u;
    asm("cvt.rna.tf32.f32 %0, %1;" : "=r"(u) : "f"(f));
    return u;
}
__device__ __forceinline__ void cp16(unsigned saddr, const void* g) {
    asm volatile("cp.async.cg.shared.global [%0], [%1], 16;\n"
                 :: "r"(saddr), "l"(g) : "memory");
}
__device__ __forceinline__ void ldsm4(unsigned r[4], unsigned saddr) {
    asm volatile("ldmatrix.sync.aligned.m8n8.x4.shared.b16 {%0,%1,%2,%3}, [%4];\n"
                 : "=r"(r[0]), "=r"(r[1]), "=r"(r[2]), "=r"(r[3]) : "r"(saddr));
}
__device__ __forceinline__ void mma_tf32(float c[4], const unsigned a[4],
                                         unsigned b0, unsigned b1) {
    asm volatile(
        "mma.sync.aligned.m16n8k8.row.col.f32.tf32.tf32.f32 "
        "{%0,%1,%2,%3}, {%4,%5,%6,%7}, {%8,%9}, {%0,%1,%2,%3};\n"
        : "+f"(c[0]), "+f"(c[1]), "+f"(c[2]), "+f"(c[3])
        : "r"(a[0]), "r"(a[1]), "r"(a[2]), "r"(a[3]), "r"(b0), "r"(b1));
}

// ---------------------------------------------------------------------------
// k0: zero out-region + seg scratch; detect idx dtype; round W1 to tf32.
// ---------------------------------------------------------------------------
__global__ void k0_init(float* __restrict__ out, const void* __restrict__ idxp,
                        const float* __restrict__ W1) {
    long long i = (long long)blockIdx.x * blockDim.x + threadIdx.x;
    if (i < NSEG * D) out[i] = 0.0f;
    if (i < NSEG) { g_segsum[i] = 0.0f; g_segmaxb[i] = 0u; }
    if (i < D * D) g_w1r[i] = __uint_as_float(f2tf(W1[i]));
    if (i == 0) {
        const long long* p64 = (const long long*)idxp;
        long long a = p64[NROWS / 4];
        long long b = p64[NROWS / 8];
        g_is64 = (a >= 0 && a < NSEG && b >= 0 && b < NSEG) ? 1 : 0;
    }
}

// ---------------------------------------------------------------------------
// k1: MLP scores via tf32 tensor cores. Block tile 128x128x128, 8 warps of
// m32 x n64 (mma.m16n8k8). cp.async double-buffered x chunks (K=64 each).
// Epilogue: bias + tanh + dot(W2) + block reduce + segmented atomicMax.
// ---------------------------------------------------------------------------
__global__ __launch_bounds__(256, 1) void k1_mlp(
    const float* __restrict__ x,
    const float* __restrict__ b1, const float* __restrict__ W2,
    const float* __restrict__ b2, const void* __restrict__ idxp)
{
    extern __shared__ float sm[];
    float* ws    = sm;                     // [128][WPAD] tf32-rounded W1, k-major
    float* xs0   = sm + 128 * WPAD;        // [128][XPAD] x rows, k 0..63
    float* xs1   = xs0 + 128 * XPAD;       // [128][XPAD] x rows, k 64..127
    float* sred  = xs1 + 128 * XPAD;       // [128]
    float* s_val = sred + 128;             // [128]
    int*   s_seg = (int*)(s_val + 128);    // [128]

    const int tid  = threadIdx.x;
    const int lane = tid & 31;
    const int warp = tid >> 5;
    const int gid  = lane >> 2;
    const int tig  = lane & 3;
    const int m0   = (warp >> 1) * 32;
    const int n0   = (warp & 1) * 64;
    const size_t row0 = (size_t)blockIdx.x * 128;
    const int is64 = g_is64;

    if (tid < 128) sred[tid] = 0.0f;

    const unsigned s_ws  = (unsigned)__cvta_generic_to_shared(ws);
    const unsigned s_xs0 = (unsigned)__cvta_generic_to_shared(xs0);
    const unsigned s_xs1 = (unsigned)__cvta_generic_to_shared(xs1);

    // ---- async prologue: xs0 + ws (group0), xs1 (group1) ----
#pragma unroll
    for (int i = 0; i < 8; i++) {           // xs0: 128 rows x 16 float4
        int q = tid + i * 256;
        int r = q >> 4, c4 = q & 15;
        cp16(s_xs0 + (unsigned)(r * XPAD + c4 * 4) * 4u,
             x + (row0 + r) * D + c4 * 4);
    }
#pragma unroll
    for (int i = 0; i < 16; i++) {          // ws: 128 rows x 32 float4
        int q = tid + i * 256;
        int r = q >> 5, c4 = q & 31;
        cp16(s_ws + (unsigned)(r * WPAD + c4 * 4) * 4u,
             g_w1r + r * D + c4 * 4);
    }
    asm volatile("cp.async.commit_group;\n" ::: "memory");
#pragma unroll
    for (int i = 0; i < 8; i++) {           // xs1
        int q = tid + i * 256;
        int r = q >> 4, c4 = q & 15;
        cp16(s_xs1 + (unsigned)(r * XPAD + c4 * 4) * 4u,
             x + (row0 + r) * D + 64 + c4 * 4);
    }
    asm volatile("cp.async.commit_group;\n" ::: "memory");

    float c[2][8][4];
#pragma unroll
    for (int mi = 0; mi < 2; mi++)
#pragma unroll
        for (int nj = 0; nj < 8; nj++)
#pragma unroll
            for (int r = 0; r < 4; r++) c[mi][nj][r] = 0.0f;

    asm volatile("cp.async.wait_group 1;\n" ::: "memory");
    __syncthreads();

    // ---- mainloop: 2 chunks x 8 k-steps of k8 ----
#pragma unroll
    for (int p = 0; p < 2; p++) {
        const unsigned xb = p ? s_xs1 : s_xs0;
#pragma unroll
        for (int kk = 0; kk < 8; kk++) {
            unsigned af[2][4];
#pragma unroll
            for (int mi = 0; mi < 2; mi++) {
                int arow = m0 + mi * 16 + (lane & 15);
                int acol = kk * 8 + ((lane >> 4) << 2);
                ldsm4(af[mi], xb + (unsigned)(arow * XPAD + acol) * 4u);
#pragma unroll
                for (int j = 0; j < 4; j++)
                    af[mi][j] = f2tf(__uint_as_float(af[mi][j]));
            }
            const int kr = p * 64 + kk * 8;
#pragma unroll
            for (int nj = 0; nj < 8; nj++) {
                int coln = n0 + nj * 8 + gid;
                unsigned b0 = __float_as_uint(ws[(kr + tig) * WPAD + coln]);
                unsigned b1r = __float_as_uint(ws[(kr + tig + 4) * WPAD + coln]);
                mma_tf32(c[0][nj], af[0], b0, b1r);
                mma_tf32(c[1][nj], af[1], b0, b1r);
            }
        }
        if (p == 0) {
            asm volatile("cp.async.wait_group 0;\n" ::: "memory");
            __syncthreads();
        }
    }

    // ---- epilogue: bias + tanh + dot(W2), reduce to per-row score ----
    float b1v[8][2], w2v[8][2];
#pragma unroll
    for (int nj = 0; nj < 8; nj++)
#pragma unroll
        for (int cc = 0; cc < 2; cc++) {
            int col = n0 + nj * 8 + tig * 2 + cc;
            b1v[nj][cc] = b1[col];
            w2v[nj][cc] = W2[col];
        }

    float rp[4] = {0.0f, 0.0f, 0.0f, 0.0f};
#pragma unroll
    for (int mi = 0; mi < 2; mi++)
#pragma unroll
        for (int nj = 0; nj < 8; nj++)
#pragma unroll
            for (int r = 0; r < 4; r++) {
                float h = tanh_fast(c[mi][nj][r] + b1v[nj][r & 1]);
                rp[mi * 2 + (r >> 1)] = fmaf(h, w2v[nj][r & 1], rp[mi * 2 + (r >> 1)]);
            }
#pragma unroll
    for (int i = 0; i < 4; i++) {
        rp[i] += __shfl_xor_sync(0xffffffffu, rp[i], 1);
        rp[i] += __shfl_xor_sync(0xffffffffu, rp[i], 2);
    }
    if (tig == 0) {
#pragma unroll
        for (int i = 0; i < 4; i++) {
            int row = m0 + (i >> 1) * 16 + (i & 1) * 8 + gid;
            atomicAdd(&sred[row], rp[i]);
        }
    }
    __syncthreads();

    if (tid < 128) {
        float sv = sred[tid] + b2[0];
        g_s[row0 + tid] = sv;
        s_val[tid] = sv;
        s_seg[tid] = seg_at(idxp, is64, row0 + tid);
    }
    __syncthreads();

    // segmented max: rows sorted by seg -> one atomic per run
    if (tid < 128) {
        int seg = s_seg[tid];
        if (tid == 0 || s_seg[tid - 1] != seg) {
            float m = s_val[tid];
            int j = tid + 1;
            while (j < 128 && s_seg[j] == seg) { m = fmaxf(m, s_val[j]); j++; }
            atomicMax(&g_segmaxb[seg], fmap(m));
        }
    }
}

// ---------------------------------------------------------------------------
// k2: e = exp(s - seg_max[idx]); smem bucket aggregation of seg_sum.
// ---------------------------------------------------------------------------
__global__ __launch_bounds__(256) void k2_exp(
    const void* __restrict__ idxp, float* __restrict__ e_out)
{
    __shared__ float buck[1024];
    const int tid = threadIdx.x;
    const long long base = (long long)blockIdx.x * 1024;
    const long long last = min(base + 1023LL, (long long)NROWS - 1);
    const int is64 = g_is64;
    const int seg_lo = seg_at(idxp, is64, base);
    const int seg_hi = seg_at(idxp, is64, last);
    const int range = seg_hi - seg_lo + 1;
    const bool use_smem = (range > 0 && range <= 1024);
    if (use_smem)
        for (int k = tid; k < range; k += 256) buck[k] = 0.0f;
    __syncthreads();

    for (int j = tid; j < 1024; j += 256) {
        long long r = base + j;
        if (r >= NROWS) break;
        int seg = seg_at(idxp, is64, r);
        float smax = funmap(g_segmaxb[seg]);
        float e = __expf(g_s[r] - smax);
        e_out[r] = e;
        if (use_smem) atomicAdd(&buck[seg - seg_lo], e);
        else          atomicAdd(&g_segsum[seg], e);
    }
    __syncthreads();

    if (use_smem)
        for (int k = tid; k < range; k += 256) {
            float v = buck[k];
            if (v != 0.0f) atomicAdd(&g_segsum[seg_lo + k], v);
        }
}

// ---------------------------------------------------------------------------
// k3: alpha = e/(seg_sum+1e-16); out += x*alpha with register accumulation.
// ---------------------------------------------------------------------------
__global__ __launch_bounds__(128) void k3_agg(
    const float* __restrict__ x, const void* __restrict__ idxp,
    float* __restrict__ alpha, float* __restrict__ out)
{
    __shared__ float sa[512];
    __shared__ int   sseg[512];
    const int tid = threadIdx.x;
    const long long base = (long long)blockIdx.x * 512;
    const int nrows = (int)min(512LL, (long long)NROWS - base);
    const int is64 = g_is64;

    for (int j = tid; j < nrows; j += 128) {
        int seg = seg_at(idxp, is64, base + j);
        float e = alpha[base + j];
        float a = __fdividef(e, g_segsum[seg] + 1e-16f);
        sa[j] = a;
        sseg[j] = seg;
        alpha[base + j] = a;
    }
    __syncthreads();

    float acc = 0.0f;
    int cur = sseg[0];
    for (int j = 0; j < nrows; j++) {
        int sg = sseg[j];
        if (sg != cur) {
            atomicAdd(&out[(size_t)cur * D + tid], acc);
            acc = 0.0f;
            cur = sg;
        }
        acc = fmaf(x[(size_t)(base + j) * D + tid], sa[j], acc);
    }
    atomicAdd(&out[(size_t)cur * D + tid], acc);
}

// ---------------------------------------------------------------------------
extern "C" void kernel_launch(void* const* d_in, const int* in_sizes, int n_in,
                              void* d_out, int out_size)
{
    const float* x  = (const float*)d_in[0];
    const float* W1 = (const float*)d_in[1];
    const float* b1 = (const float*)d_in[2];
    const float* W2 = (const float*)d_in[3];
    const float* b2 = (const float*)d_in[4];
    const void*  idxp = d_in[5];

    float* outp  = (float*)d_out;          // (4096, 128)
    float* alpha = outp + NSEG * D;        // (N, 1) -- holds e between k2/k3

    cudaFuncSetAttribute(k1_mlp, cudaFuncAttributeMaxDynamicSharedMemorySize,
                         K1_SMEM_BYTES);

    k0_init<<<(NSEG * D + 255) / 256, 256>>>(outp, idxp, W1);
    k1_mlp <<<NROWS / 128, 256, K1_SMEM_BYTES>>>(x, b1, W2, b2, idxp);
    k2_exp <<<(NROWS + 1023) / 1024, 256>>>(idxp, alpha);
    k3_agg <<<(NROWS + 511) / 512, 128>>>(x, idxp, alpha, outp);
}

// round 5
// speedup vs baseline: 1.6067x; 1.1783x over previous
#include <cuda_runtime.h>
#include <cuda_fp16.h>
#include <cstdint>

#define NROWS 2000000
#define D 128
#define NSEG 4096
#define NTILES (NROWS / 128)          // 15625

// ---- k1 dynamic smem layout (bytes) ----
// ws:    half Wt[128 n][136 half]  (stride 272B, 17 chunks)   34816
// stage: fp32 x  [128 r][132 f32]  (stride 528B, 33 chunks)   67584
// xh[2]: half x  [128 r][136 half] (stride 272B)            2x34816
// misc:  bw float2[128], sred[128], sval[128], sseg[128]       2560
#define WS_OFF    0
#define STAGE_OFF 34816
#define XH0_OFF   102400
#define XH1_OFF   137216
#define MISC_OFF  172032
#define SMEM_TOTAL (172032 + 2560)

#define WSTR 136   // half stride of ws/xh rows
#define SSTR 132   // float stride of stage rows

// ---- scratch (no allocations allowed) ----
__device__ float    g_s[NROWS];
__device__ float    g_segsum[NSEG];
__device__ unsigned g_segmaxb[NSEG];
__device__ int      g_is64;
__device__ __half   g_w1h[D * D];   // W1^T as half: g_w1h[n*128+k] = W1[k][n]

// ---- helpers ----
__device__ __forceinline__ int seg_at(const void* p, int is64, long long i) {
    int v = is64 ? (int)((const long long*)p)[i] : ((const int*)p)[i];
    return min(max(v, 0), NSEG - 1);
}
__device__ __forceinline__ unsigned fmap(float f) {
    unsigned u = __float_as_uint(f);
    return (u & 0x80000000u) ? ~u : (u | 0x80000000u);
}
__device__ __forceinline__ float funmap(unsigned m) {
    return (m & 0x80000000u) ? __uint_as_float(m ^ 0x80000000u)
                             : __uint_as_float(~m);
}
__device__ __forceinline__ float tanh_fast(float v) {
    float e = __expf(2.0f * v);
    return 1.0f - __fdividef(2.0f, e + 1.0f);
}
__device__ __forceinline__ void cp16(unsigned saddr, const void* g) {
    asm volatile("cp.async.cg.shared.global [%0], [%1], 16;\n"
                 :: "r"(saddr), "l"(g) : "memory");
}
__device__ __forceinline__ void cp_commit() {
    asm volatile("cp.async.commit_group;\n" ::: "memory");
}
__device__ __forceinline__ void cp_wait0() {
    asm volatile("cp.async.wait_group 0;\n" ::: "memory");
}
__device__ __forceinline__ void ldsm4(unsigned r[4], unsigned saddr) {
    asm volatile("ldmatrix.sync.aligned.m8n8.x4.shared.b16 {%0,%1,%2,%3}, [%4];\n"
                 : "=r"(r[0]), "=r"(r[1]), "=r"(r[2]), "=r"(r[3]) : "r"(saddr));
}
__device__ __forceinline__ void mma16816(float c[4], const unsigned a[4],
                                         unsigned b0, unsigned b1) {
    asm volatile(
        "mma.sync.aligned.m16n8k16.row.col.f32.f16.f16.f32 "
        "{%0,%1,%2,%3}, {%4,%5,%6,%7}, {%8,%9}, {%0,%1,%2,%3};\n"
        : "+f"(c[0]), "+f"(c[1]), "+f"(c[2]), "+f"(c[3])
        : "r"(a[0]), "r"(a[1]), "r"(a[2]), "r"(a[3]), "r"(b0), "r"(b1));
}

// ---------------------------------------------------------------------------
// k0: zero out + seg scratch; detect idx dtype; pack W1^T as half (n-major).
// ---------------------------------------------------------------------------
__global__ void k0_init(float* __restrict__ out, const void* __restrict__ idxp,
                        const float* __restrict__ W1) {
    long long i = (long long)blockIdx.x * blockDim.x + threadIdx.x;
    if (i < NSEG * D) out[i] = 0.0f;
    if (i < NSEG) { g_segsum[i] = 0.0f; g_segmaxb[i] = 0u; }
    if (i < D * D) {
        int n = (int)(i / D), k = (int)(i % D);
        g_w1h[i] = __float2half_rn(W1[(size_t)k * D + n]);
    }
    if (i == 0) {
        const long long* p64 = (const long long*)idxp;
        long long a = p64[NROWS / 4];
        long long b = p64[NROWS / 8];
        g_is64 = (a >= 0 && a < NSEG && b >= 0 && b < NSEG) ? 1 : 0;
    }
}

// ---------------------------------------------------------------------------
// k1: persistent fp16-mma MLP. 512 threads (16 warps: warp tile m32 x n32).
// cp.async fp32 stage -> smem half convert -> ldmatrix -> mma.m16n8k16.
// Epilogue: bias + tanh + dot(W2) + block reduce + segmented atomicMax.
// ---------------------------------------------------------------------------
__global__ __launch_bounds__(512, 1)
void k1_mlp(const float* __restrict__ x,
            const float* __restrict__ b1, const float* __restrict__ W2,
            const float* __restrict__ b2, const void* __restrict__ idxp)
{
    extern __shared__ char sm[];
    float*  stagef = (float*)(sm + STAGE_OFF);
    float2* bwp  = (float2*)(sm + MISC_OFF);
    float*  sred = (float*)(sm + MISC_OFF + 1024);
    float*  sval = (float*)(sm + MISC_OFF + 1536);
    int*    sseg = (int*)(sm + MISC_OFF + 2048);

    const unsigned s_base  = (unsigned)__cvta_generic_to_shared(sm);
    const unsigned s_ws    = s_base + WS_OFF;
    const unsigned s_stage = s_base + STAGE_OFF;
    const unsigned s_xh[2] = { s_base + XH0_OFF, s_base + XH1_OFF };

    const int tid  = threadIdx.x;
    const int lane = tid & 31;
    const int warp = tid >> 5;
    const int gid  = lane >> 2;          // l/4
    const int tig  = lane & 3;           // l%4
    const int m0   = (warp & 3) * 32;
    const int n0   = (warp >> 2) * 32;
    const int grid = gridDim.x;
    const int cta  = blockIdx.x;
    const int n_t  = (NTILES - cta + grid - 1) / grid;
    const int is64 = g_is64;

    // convert-pass mapping: thread -> (row, 32-col quarter)
    const int cv_row = tid & 127;
    const int cv_c0  = (tid >> 7) * 32;

    // ldmatrix base addresses (byte offsets inside buffers)
    const unsigned a_off = (unsigned)((m0 + (lane & 15)) * (WSTR * 2) + ((lane >> 4) * 16));
    const unsigned b_off = (unsigned)((n0 + (lane & 7) + ((lane >> 4) << 3)) * (WSTR * 2)
                                      + (((lane >> 3) & 1) * 16));

    if (tid < 128) {
        bwp[tid] = make_float2(b1[tid], W2[tid]);
        sred[tid] = 0.0f;
    }
    const float b2v = b2[0];

    // ---- prologue: ws (2048 chunks) + stage tile0 (4096 chunks) ----
    if (n_t > 0) {
#pragma unroll
        for (int c = 0; c < 4; c++) {
            int q = tid + c * 512;
            int r = q >> 4, cc = q & 15;
            cp16(s_ws + (unsigned)(r * (WSTR * 2) + cc * 16),
                 g_w1h + (size_t)r * D + cc * 8);
        }
        const float* xb = x + (size_t)cta * 128 * D;
#pragma unroll
        for (int c = 0; c < 8; c++) {
            int q = tid + c * 512;
            int r = q >> 5, cc = q & 31;
            cp16(s_stage + (unsigned)(r * (SSTR * 4) + cc * 16),
                 xb + (size_t)r * D + cc * 4);
        }
        cp_commit();
        cp_wait0();
        __syncthreads();

        // convert stage -> xh[0]
        {
            const float4* src = (const float4*)(stagef + (size_t)cv_row * SSTR + cv_c0);
            uint4* dst = (uint4*)(sm + XH0_OFF + (size_t)cv_row * (WSTR * 2) + cv_c0 * 2);
#pragma unroll
            for (int j = 0; j < 4; j++) {
                float4 v0 = src[j * 2], v1 = src[j * 2 + 1];
                __half2 h0 = __floats2half2_rn(v0.x, v0.y);
                __half2 h1 = __floats2half2_rn(v0.z, v0.w);
                __half2 h2 = __floats2half2_rn(v1.x, v1.y);
                __half2 h3 = __floats2half2_rn(v1.z, v1.w);
                uint4 u;
                u.x = *(unsigned*)&h0; u.y = *(unsigned*)&h1;
                u.z = *(unsigned*)&h2; u.w = *(unsigned*)&h3;
                dst[j] = u;
            }
        }
        __syncthreads();

        if (n_t > 1) {   // prefetch tile1 into stage
            const float* xb1 = x + ((size_t)cta + grid) * 128 * D;
#pragma unroll
            for (int c = 0; c < 8; c++) {
                int q = tid + c * 512;
                int r = q >> 5, cc = q & 31;
                cp16(s_stage + (unsigned)(r * (SSTR * 4) + cc * 16),
                     xb1 + (size_t)r * D + cc * 4);
            }
            cp_commit();
        }
    }

    for (int i = 0; i < n_t; i++) {
        const int b = i & 1;
        const unsigned xa = s_xh[b] + a_off;
        const unsigned bb = s_ws + b_off;

        // ---- mainloop: 8 k16 steps, warp tile m32 x n32 ----
        float c[2][4][4];
#pragma unroll
        for (int mi = 0; mi < 2; mi++)
#pragma unroll
            for (int nj = 0; nj < 4; nj++)
#pragma unroll
                for (int r = 0; r < 4; r++) c[mi][nj][r] = 0.0f;

#pragma unroll
        for (int k0 = 0; k0 < 8; k0++) {
            unsigned af[2][4], bf[2][4];
            ldsm4(af[0], xa + k0 * 32);
            ldsm4(af[1], xa + 16 * (WSTR * 2) + k0 * 32);
            ldsm4(bf[0], bb + k0 * 32);
            ldsm4(bf[1], bb + 16 * (WSTR * 2) + k0 * 32);
#pragma unroll
            for (int mi = 0; mi < 2; mi++)
#pragma unroll
                for (int nj2 = 0; nj2 < 2; nj2++) {
                    mma16816(c[mi][nj2 * 2],     af[mi], bf[nj2][0], bf[nj2][1]);
                    mma16816(c[mi][nj2 * 2 + 1], af[mi], bf[nj2][2], bf[nj2][3]);
                }
        }

        // ---- pipeline: land tile i+1, convert it, prefetch tile i+2 ----
        if (i + 1 < n_t) {
            cp_wait0();
            __syncthreads();
            {
                const float4* src = (const float4*)(stagef + (size_t)cv_row * SSTR + cv_c0);
                uint4* dst = (uint4*)(sm + (b ? XH0_OFF : XH1_OFF)
                                      + (size_t)cv_row * (WSTR * 2) + cv_c0 * 2);
#pragma unroll
                for (int j = 0; j < 4; j++) {
                    float4 v0 = src[j * 2], v1 = src[j * 2 + 1];
                    __half2 h0 = __floats2half2_rn(v0.x, v0.y);
                    __half2 h1 = __floats2half2_rn(v0.z, v0.w);
                    __half2 h2 = __floats2half2_rn(v1.x, v1.y);
                    __half2 h3 = __floats2half2_rn(v1.z, v1.w);
                    uint4 u;
                    u.x = *(unsigned*)&h0; u.y = *(unsigned*)&h1;
                    u.z = *(unsigned*)&h2; u.w = *(unsigned*)&h3;
                    dst[j] = u;
                }
            }
            __syncthreads();
            if (i + 2 < n_t) {
                const float* xb = x + ((size_t)cta + (size_t)(i + 2) * grid) * 128 * D;
#pragma unroll
                for (int cc2 = 0; cc2 < 8; cc2++) {
                    int q = tid + cc2 * 512;
                    int r = q >> 5, cc = q & 31;
                    cp16(s_stage + (unsigned)(r * (SSTR * 4) + cc * 16),
                         xb + (size_t)r * D + cc * 4);
                }
                cp_commit();
            }
        }

        // ---- epilogue: bias + tanh + dot(W2) -> per-row score ----
        float b1v[4][2], w2v[4][2];
#pragma unroll
        for (int nj = 0; nj < 4; nj++)
#pragma unroll
            for (int cc = 0; cc < 2; cc++) {
                float2 bw = bwp[n0 + nj * 8 + tig * 2 + cc];
                b1v[nj][cc] = bw.x;
                w2v[nj][cc] = bw.y;
            }

        float rp[4] = {0.0f, 0.0f, 0.0f, 0.0f};
#pragma unroll
        for (int mi = 0; mi < 2; mi++)
#pragma unroll
            for (int nj = 0; nj < 4; nj++)
#pragma unroll
                for (int r = 0; r < 4; r++) {
                    float h = tanh_fast(c[mi][nj][r] + b1v[nj][r & 1]);
                    rp[mi * 2 + (r >> 1)] = fmaf(h, w2v[nj][r & 1], rp[mi * 2 + (r >> 1)]);
                }
#pragma unroll
        for (int q = 0; q < 4; q++) {
            rp[q] += __shfl_xor_sync(0xffffffffu, rp[q], 1);
            rp[q] += __shfl_xor_sync(0xffffffffu, rp[q], 2);
        }
        if (tig == 0) {
#pragma unroll
            for (int q = 0; q < 4; q++) {
                int row = m0 + (q >> 1) * 16 + (q & 1) * 8 + gid;
                atomicAdd(&sred[row], rp[q]);
            }
        }
        __syncthreads();

        const size_t row0 = ((size_t)cta + (size_t)i * grid) * 128;
        if (tid < 128) {
            float sv = sred[tid] + b2v;
            g_s[row0 + tid] = sv;
            sval[tid] = sv;
            sseg[tid] = seg_at(idxp, is64, (long long)(row0 + tid));
            sred[tid] = 0.0f;
        }
        __syncthreads();

        if (tid < 128) {
            int seg = sseg[tid];
            if (tid == 0 || sseg[tid - 1] != seg) {
                float m = sval[tid];
                int j = tid + 1;
                while (j < 128 && sseg[j] == seg) { m = fmaxf(m, sval[j]); j++; }
                atomicMax(&g_segmaxb[seg], fmap(m));
            }
        }
        __syncthreads();
    }
}

// ---------------------------------------------------------------------------
// k2: e = exp(s - seg_max[idx]); smem bucket aggregation of seg_sum.
// ---------------------------------------------------------------------------
__global__ __launch_bounds__(256) void k2_exp(
    const void* __restrict__ idxp, float* __restrict__ e_out)
{
    __shared__ float buck[1024];
    const int tid = threadIdx.x;
    const long long base = (long long)blockIdx.x * 1024;
    const long long last = min(base + 1023LL, (long long)NROWS - 1);
    const int is64 = g_is64;
    const int seg_lo = seg_at(idxp, is64, base);
    const int seg_hi = seg_at(idxp, is64, last);
    const int range = seg_hi - seg_lo + 1;
    const bool use_smem = (range > 0 && range <= 1024);
    if (use_smem)
        for (int k = tid; k < range; k += 256) buck[k] = 0.0f;
    __syncthreads();

    for (int j = tid; j < 1024; j += 256) {
        long long r = base + j;
        if (r >= NROWS) break;
        int seg = seg_at(idxp, is64, r);
        float smax = funmap(g_segmaxb[seg]);
        float e = __expf(g_s[r] - smax);
        e_out[r] = e;
        if (use_smem) atomicAdd(&buck[seg - seg_lo], e);
        else          atomicAdd(&g_segsum[seg], e);
    }
    __syncthreads();

    if (use_smem)
        for (int k = tid; k < range; k += 256) {
            float v = buck[k];
            if (v != 0.0f) atomicAdd(&g_segsum[seg_lo + k], v);
        }
}

// ---------------------------------------------------------------------------
// k3: alpha = e/(seg_sum+1e-16); out += x*alpha with register accumulation.
// ---------------------------------------------------------------------------
__global__ __launch_bounds__(128) void k3_agg(
    const float* __restrict__ x, const void* __restrict__ idxp,
    float* __restrict__ alpha, float* __restrict__ out)
{
    __shared__ float sa[512];
    __shared__ int   sseg[512];
    const int tid = threadIdx.x;
    const long long base = (long long)blockIdx.x * 512;
    const int nrows = (int)min(512LL, (long long)NROWS - base);
    const int is64 = g_is64;

    for (int j = tid; j < nrows; j += 128) {
        int seg = seg_at(idxp, is64, base + j);
        float e = alpha[base + j];
        float a = __fdividef(e, g_segsum[seg] + 1e-16f);
        sa[j] = a;
        sseg[j] = seg;
        alpha[base + j] = a;
    }
    __syncthreads();

    float acc = 0.0f;
    int cur = sseg[0];
    for (int j = 0; j < nrows; j++) {
        int sg = sseg[j];
        if (sg != cur) {
            atomicAdd(&out[(size_t)cur * D + tid], acc);
            acc = 0.0f;
            cur = sg;
        }
        acc = fmaf(x[(size_t)(base + j) * D + tid], sa[j], acc);
    }
    atomicAdd(&out[(size_t)cur * D + tid], acc);
}

// ---------------------------------------------------------------------------
extern "C" void kernel_launch(void* const* d_in, const int* in_sizes, int n_in,
                              void* d_out, int out_size)
{
    const float* x  = (const float*)d_in[0];
    const float* W1 = (const float*)d_in[1];
    const float* b1 = (const float*)d_in[2];
    const float* W2 = (const float*)d_in[3];
    const float* b2 = (const float*)d_in[4];
    const void*  idxp = d_in[5];

    float* outp  = (float*)d_out;          // (4096, 128)
    float* alpha = outp + NSEG * D;        // (N, 1) -- holds e between k2/k3

    static int sms = 0;
    if (!sms) {
        cudaDeviceGetAttribute(&sms, cudaDevAttrMultiProcessorCount, 0);
        cudaFuncSetAttribute(k1_mlp, cudaFuncAttributeMaxDynamicSharedMemorySize,
                             SMEM_TOTAL);
    }

    k0_init<<<(NSEG * D + 255) / 256, 256>>>(outp, idxp, W1);
    k1_mlp <<<sms, 512, SMEM_TOTAL>>>(x, b1, W2, b2, idxp);
    k2_exp <<<(NROWS + 1023) / 1024, 256>>>(idxp, alpha);
    k3_agg <<<(NROWS + 511) / 512, 128>>>(x, idxp, alpha, outp);
}

// round 6
// speedup vs baseline: 1.7227x; 1.0722x over previous
#include <cuda_runtime.h>
#include <cuda_fp16.h>
#include <cstdint>

#define NROWS 2000000
#define D 128
#define NSEG 4096
#define NTILES (NROWS / 128)          // 15625

// ---- k1 dynamic smem layout (bytes) ----
// ws:    half Wt[128 n][136 half] (stride 272B)               34816
// xh[2]: half x  [128 r][136 half] (stride 272B)            2x34816
// misc:  bw float2[128], sred[128], sval[128], sseg[128]       2560
#define WS_OFF    0
#define XH0_OFF   34816
#define XH1_OFF   69632
#define MISC_OFF  104448
#define SMEM_TOTAL (104448 + 2560)

#define WSTR 136   // half stride of ws/xh rows (272 B)

// ---- scratch (no allocations allowed) ----
__device__ float    g_s[NROWS];
__device__ float    g_segsum[NSEG];
__device__ unsigned g_segmaxb[NSEG];
__device__ int      g_is64;
__device__ __half   g_w1h[D * D];   // W1^T as half: g_w1h[n*128+k] = W1[k][n]

// ---- helpers ----
__device__ __forceinline__ int seg_at(const void* p, int is64, long long i) {
    int v = is64 ? (int)((const long long*)p)[i] : ((const int*)p)[i];
    return min(max(v, 0), NSEG - 1);
}
__device__ __forceinline__ unsigned fmap(float f) {
    unsigned u = __float_as_uint(f);
    return (u & 0x80000000u) ? ~u : (u | 0x80000000u);
}
__device__ __forceinline__ float funmap(unsigned m) {
    return (m & 0x80000000u) ? __uint_as_float(m ^ 0x80000000u)
                             : __uint_as_float(~m);
}
__device__ __forceinline__ float tanh_hw(float v) {
    float r;
    asm("tanh.approx.f32 %0, %1;" : "=f"(r) : "f"(v));
    return r;
}
__device__ __forceinline__ void cp16(unsigned saddr, const void* g) {
    asm volatile("cp.async.cg.shared.global [%0], [%1], 16;\n"
                 :: "r"(saddr), "l"(g) : "memory");
}
__device__ __forceinline__ void cp_commit() {
    asm volatile("cp.async.commit_group;\n" ::: "memory");
}
__device__ __forceinline__ void cp_wait0() {
    asm volatile("cp.async.wait_group 0;\n" ::: "memory");
}
__device__ __forceinline__ void ldsm4(unsigned r[4], unsigned saddr) {
    asm volatile("ldmatrix.sync.aligned.m8n8.x4.shared.b16 {%0,%1,%2,%3}, [%4];\n"
                 : "=r"(r[0]), "=r"(r[1]), "=r"(r[2]), "=r"(r[3]) : "r"(saddr));
}
__device__ __forceinline__ void mma16816(float c[4], const unsigned a[4],
                                         unsigned b0, unsigned b1) {
    asm volatile(
        "mma.sync.aligned.m16n8k16.row.col.f32.f16.f16.f32 "
        "{%0,%1,%2,%3}, {%4,%5,%6,%7}, {%8,%9}, {%0,%1,%2,%3};\n"
        : "+f"(c[0]), "+f"(c[1]), "+f"(c[2]), "+f"(c[3])
        : "r"(a[0]), "r"(a[1]), "r"(a[2]), "r"(a[3]), "r"(b0), "r"(b1));
}
// convert 2 float4 -> 8 halves packed in uint2
__device__ __forceinline__ uint2 pack8(float4 v0, float4 v1) {
    __half2 h0 = __floats2half2_rn(v0.x, v0.y);
    __half2 h1 = __floats2half2_rn(v0.z, v0.w);
    uint2 u;
    u.x = (*(unsigned*)&h0) | 0u; u.y = *(unsigned*)&h1;
    (void)v1;
    return u;
}

// ---------------------------------------------------------------------------
// k0: zero out + seg scratch; detect idx dtype; pack W1^T as half (n-major).
// ---------------------------------------------------------------------------
__global__ void k0_init(float* __restrict__ out, const void* __restrict__ idxp,
                        const float* __restrict__ W1) {
    long long i = (long long)blockIdx.x * blockDim.x + threadIdx.x;
    if (i < NSEG * D) out[i] = 0.0f;
    if (i < NSEG) { g_segsum[i] = 0.0f; g_segmaxb[i] = 0u; }
    if (i < D * D) {
        int n = (int)(i / D), k = (int)(i % D);
        g_w1h[i] = __float2half_rn(W1[(size_t)k * D + n]);
    }
    if (i == 0) {
        const long long* p64 = (const long long*)idxp;
        long long a = p64[NROWS / 4];
        long long b = p64[NROWS / 8];
        g_is64 = (a >= 0 && a < NSEG && b >= 0 && b < NSEG) ? 1 : 0;
    }
}

// ---------------------------------------------------------------------------
// k1: persistent fp16-mma MLP. 512 threads, 16 warps (warp tile m32 x n32).
// LDG.128 prefetch -> register convert -> STS.64 (no cp.async staging).
// ---------------------------------------------------------------------------
__global__ __launch_bounds__(512, 1)
void k1_mlp(const float* __restrict__ x,
            const float* __restrict__ b1, const float* __restrict__ W2,
            const float* __restrict__ b2, const void* __restrict__ idxp)
{
    extern __shared__ char sm[];
    float2* bwp  = (float2*)(sm + MISC_OFF);
    float*  sred = (float*)(sm + MISC_OFF + 1024);
    float*  sval = (float*)(sm + MISC_OFF + 1536);
    int*    sseg = (int*)(sm + MISC_OFF + 2048);

    const unsigned s_base  = (unsigned)__cvta_generic_to_shared(sm);
    const unsigned s_ws    = s_base + WS_OFF;
    const unsigned s_xh[2] = { s_base + XH0_OFF, s_base + XH1_OFF };

    const int tid  = threadIdx.x;
    const int lane = tid & 31;
    const int warp = tid >> 5;
    const int gid  = lane >> 2;
    const int tig  = lane & 3;
    const int m0   = (warp & 3) * 32;
    const int n0   = (warp >> 2) * 32;
    const int grid = gridDim.x;
    const int cta  = blockIdx.x;
    const int n_t  = (NTILES - cta + grid - 1) / grid;
    const int is64 = g_is64;

    // convert/store mapping: thread handles float4-chunks c = tid + j*512,
    // row = (tid>>5) + 16*j, 16B-chunk cc = tid&31 -> 8B half chunk
    const int cv_r0 = tid >> 5;
    const int cv_cc = tid & 31;

    // ldmatrix base byte offsets (within xh / ws)
    const unsigned a_off = (unsigned)((m0 + (lane & 15)) * (WSTR * 2) + ((lane >> 4) * 16));
    const unsigned b_off = (unsigned)((n0 + (lane & 7) + ((lane >> 4) << 3)) * (WSTR * 2)
                                      + (((lane >> 3) & 1) * 16));

    if (tid < 128) {
        bwp[tid] = make_float2(b1[tid], W2[tid]);
        sred[tid] = 0.0f;
    }
    const float b2v = b2[0];

    if (n_t == 0) return;

    // ---- prologue: ws via cp.async (one-time), tile0 via LDG->cvt->STS ----
#pragma unroll
    for (int c = 0; c < 4; c++) {
        int q = tid + c * 512;
        int r = q >> 4, cc = q & 15;
        cp16(s_ws + (unsigned)(r * (WSTR * 2) + cc * 16),
             g_w1h + (size_t)r * D + cc * 8);
    }
    cp_commit();
    {
        const float4* xb = (const float4*)(x + (size_t)cta * 128 * D);
        float4 rv[8];
#pragma unroll
        for (int j = 0; j < 8; j++) rv[j] = xb[tid + j * 512];
        cp_wait0();
        __syncthreads();   // ws ready; also orders smem init
#pragma unroll
        for (int j = 0; j < 8; j++) {
            __half2 h0 = __floats2half2_rn(rv[j].x, rv[j].y);
            __half2 h1 = __floats2half2_rn(rv[j].z, rv[j].w);
            uint2 u = { *(unsigned*)&h0, *(unsigned*)&h1 };
            *(uint2*)(sm + XH0_OFF + (size_t)(cv_r0 + 16 * j) * (WSTR * 2) + cv_cc * 8) = u;
        }
        __syncthreads();
    }

    for (int i = 0; i < n_t; i++) {
        const int b = i & 1;
        const unsigned xa = s_xh[b] + a_off;
        const unsigned bb = s_ws + b_off;
        const bool have_next = (i + 1 < n_t);

        // ---- prefetch tile i+1 into registers (latency hides under MMA) ----
        float4 rv[8];
        if (have_next) {
            const float4* xn = (const float4*)(x + ((size_t)cta + (size_t)(i + 1) * grid) * 128 * D);
#pragma unroll
            for (int j = 0; j < 8; j++) rv[j] = xn[tid + j * 512];
        }

        // ---- mainloop: 8 k16 steps, warp tile m32 x n32 ----
        float c[2][4][4];
#pragma unroll
        for (int mi = 0; mi < 2; mi++)
#pragma unroll
            for (int nj = 0; nj < 4; nj++)
#pragma unroll
                for (int r = 0; r < 4; r++) c[mi][nj][r] = 0.0f;

#pragma unroll
        for (int k0 = 0; k0 < 8; k0++) {
            unsigned af[2][4], bf[2][4];
            ldsm4(af[0], xa + k0 * 32);
            ldsm4(af[1], xa + 16 * (WSTR * 2) + k0 * 32);
            ldsm4(bf[0], bb + k0 * 32);
            ldsm4(bf[1], bb + 16 * (WSTR * 2) + k0 * 32);
#pragma unroll
            for (int mi = 0; mi < 2; mi++)
#pragma unroll
                for (int nj2 = 0; nj2 < 2; nj2++) {
                    mma16816(c[mi][nj2 * 2],     af[mi], bf[nj2][0], bf[nj2][1]);
                    mma16816(c[mi][nj2 * 2 + 1], af[mi], bf[nj2][2], bf[nj2][3]);
                }
        }

        __syncthreads();   // everyone done reading xh[b^1] from prior iter

        // ---- store tile i+1 into xh[b^1] ----
        if (have_next) {
            char* dst = sm + (b ? XH0_OFF : XH1_OFF);
#pragma unroll
            for (int j = 0; j < 8; j++) {
                __half2 h0 = __floats2half2_rn(rv[j].x, rv[j].y);
                __half2 h1 = __floats2half2_rn(rv[j].z, rv[j].w);
                uint2 u = { *(unsigned*)&h0, *(unsigned*)&h1 };
                *(uint2*)(dst + (size_t)(cv_r0 + 16 * j) * (WSTR * 2) + cv_cc * 8) = u;
            }
        }

        // ---- epilogue: bias + hw-tanh + dot(W2) -> per-row score ----
        float b1v[4][2], w2v[4][2];
#pragma unroll
        for (int nj = 0; nj < 4; nj++)
#pragma unroll
            for (int cc = 0; cc < 2; cc++) {
                float2 bw = bwp[n0 + nj * 8 + tig * 2 + cc];
                b1v[nj][cc] = bw.x;
                w2v[nj][cc] = bw.y;
            }
        float rp[4] = {0.0f, 0.0f, 0.0f, 0.0f};
#pragma unroll
        for (int mi = 0; mi < 2; mi++)
#pragma unroll
            for (int nj = 0; nj < 4; nj++)
#pragma unroll
                for (int r = 0; r < 4; r++) {
                    float h = tanh_hw(c[mi][nj][r] + b1v[nj][r & 1]);
                    rp[mi * 2 + (r >> 1)] = fmaf(h, w2v[nj][r & 1], rp[mi * 2 + (r >> 1)]);
                }
#pragma unroll
        for (int q = 0; q < 4; q++) {
            rp[q] += __shfl_xor_sync(0xffffffffu, rp[q], 1);
            rp[q] += __shfl_xor_sync(0xffffffffu, rp[q], 2);
        }
        if (tig == 0) {
#pragma unroll
            for (int q = 0; q < 4; q++) {
                int row = m0 + (q >> 1) * 16 + (q & 1) * 8 + gid;
                atomicAdd(&sred[row], rp[q]);
            }
        }
        __syncthreads();   // sred complete + xh[b^1] stored

        const size_t row0 = ((size_t)cta + (size_t)i * grid) * 128;
        if (tid < 128) {
            float sv = sred[tid] + b2v;
            g_s[row0 + tid] = sv;
            sval[tid] = sv;
            sseg[tid] = seg_at(idxp, is64, (long long)(row0 + tid));
            sred[tid] = 0.0f;
        }
        __syncthreads();   // sval/sseg ready

        if (tid < 128) {
            int seg = sseg[tid];
            if (tid == 0 || sseg[tid - 1] != seg) {
                float m = sval[tid];
                int j = tid + 1;
                while (j < 128 && sseg[j] == seg) { m = fmaxf(m, sval[j]); j++; }
                atomicMax(&g_segmaxb[seg], fmap(m));
            }
        }
        // next iteration's first barrier orders segmax reads vs new writes
    }
}

// ---------------------------------------------------------------------------
// k2: e = exp(s - seg_max[idx]); smem bucket aggregation of seg_sum.
// ---------------------------------------------------------------------------
__global__ __launch_bounds__(256) void k2_exp(
    const void* __restrict__ idxp, float* __restrict__ e_out)
{
    __shared__ float buck[1024];
    const int tid = threadIdx.x;
    const long long base = (long long)blockIdx.x * 1024;
    const long long last = min(base + 1023LL, (long long)NROWS - 1);
    const int is64 = g_is64;
    const int seg_lo = seg_at(idxp, is64, base);
    const int seg_hi = seg_at(idxp, is64, last);
    const int range = seg_hi - seg_lo + 1;
    const bool use_smem = (range > 0 && range <= 1024);
    if (use_smem)
        for (int k = tid; k < range; k += 256) buck[k] = 0.0f;
    __syncthreads();

    for (int j = tid; j < 1024; j += 256) {
        long long r = base + j;
        if (r >= NROWS) break;
        int seg = seg_at(idxp, is64, r);
        float smax = funmap(g_segmaxb[seg]);
        float e = __expf(g_s[r] - smax);
        e_out[r] = e;
        if (use_smem) atomicAdd(&buck[seg - seg_lo], e);
        else          atomicAdd(&g_segsum[seg], e);
    }
    __syncthreads();

    if (use_smem)
        for (int k = tid; k < range; k += 256) {
            float v = buck[k];
            if (v != 0.0f) atomicAdd(&g_segsum[seg_lo + k], v);
        }
}

// ---------------------------------------------------------------------------
// k3: alpha = e/(seg_sum+1e-16); out += x*alpha with register accumulation.
// ---------------------------------------------------------------------------
__global__ __launch_bounds__(128) void k3_agg(
    const float* __restrict__ x, const void* __restrict__ idxp,
    float* __restrict__ alpha, float* __restrict__ out)
{
    __shared__ float sa[512];
    __shared__ int   sseg[512];
    const int tid = threadIdx.x;
    const long long base = (long long)blockIdx.x * 512;
    const int nrows = (int)min(512LL, (long long)NROWS - base);
    const int is64 = g_is64;

    for (int j = tid; j < nrows; j += 128) {
        int seg = seg_at(idxp, is64, base + j);
        float e = alpha[base + j];
        float a = __fdividef(e, g_segsum[seg] + 1e-16f);
        sa[j] = a;
        sseg[j] = seg;
        alpha[base + j] = a;
    }
    __syncthreads();

    float acc = 0.0f;
    int cur = sseg[0];
    for (int j = 0; j < nrows; j++) {
        int sg = sseg[j];
        if (sg != cur) {
            atomicAdd(&out[(size_t)cur * D + tid], acc);
            acc = 0.0f;
            cur = sg;
        }
        acc = fmaf(x[(size_t)(base + j) * D + tid], sa[j], acc);
    }
    atomicAdd(&out[(size_t)cur * D + tid], acc);
}

// ---------------------------------------------------------------------------
extern "C" void kernel_launch(void* const* d_in, const int* in_sizes, int n_in,
                              void* d_out, int out_size)
{
    const float* x  = (const float*)d_in[0];
    const float* W1 = (const float*)d_in[1];
    const float* b1 = (const float*)d_in[2];
    const float* W2 = (const float*)d_in[3];
    const float* b2 = (const float*)d_in[4];
    const void*  idxp = d_in[5];

    float* outp  = (float*)d_out;          // (4096, 128)
    float* alpha = outp + NSEG * D;        // (N, 1) -- holds e between k2/k3

    static int sms = 0;
    if (!sms) {
        cudaDeviceGetAttribute(&sms, cudaDevAttrMultiProcessorCount, 0);
        cudaFuncSetAttribute(k1_mlp, cudaFuncAttributeMaxDynamicSharedMemorySize,
                             SMEM_TOTAL);
    }

    k0_init<<<(NSEG * D + 255) / 256, 256>>>(outp, idxp, W1);
    k1_mlp <<<sms, 512, SMEM_TOTAL>>>(x, b1, W2, b2, idxp);
    k2_exp <<<(NROWS + 1023) / 1024, 256>>>(idxp, alpha);
    k3_agg <<<(NROWS + 511) / 512, 128>>>(x, idxp, alpha, outp);
}

// round 7
// speedup vs baseline: 3.2010x; 1.8581x over previous
#include <cuda_runtime.h>
#include <cuda_fp16.h>
#include <cstdint>

#define NROWS 2000000
#define D 128
#define NSEG 4096
#define NTILES (NROWS / 128)          // 15625

// ---- k1 dynamic smem layout (bytes) ----
// ws:    half Wt[128 n][136 half] (stride 272B)               34816
// xh[2]: half x  [128 r][136 half] (stride 272B)            2x34816
// misc:  bw float2[128], sred[128]                             1536
#define WS_OFF    0
#define XH0_OFF   34816
#define XH1_OFF   69632
#define MISC_OFF  104448
#define SMEM_TOTAL (104448 + 1536)

#define WSTR 136   // half stride of ws/xh rows (272 B)

// ---- scratch (no allocations allowed) ----
__device__ float    g_s[NROWS];
__device__ float    g_segsum[NSEG];
__device__ unsigned g_segmaxb[NSEG];
__device__ int      g_is64;
__device__ __half   g_w1h[D * D];   // W1^T as half: g_w1h[n*128+k] = W1[k][n]

// ---- helpers ----
__device__ __forceinline__ int seg_at(const void* p, int is64, long long i) {
    int v = is64 ? (int)((const long long*)p)[i] : ((const int*)p)[i];
    return min(max(v, 0), NSEG - 1);
}
__device__ __forceinline__ unsigned fmap(float f) {
    unsigned u = __float_as_uint(f);
    return (u & 0x80000000u) ? ~u : (u | 0x80000000u);
}
__device__ __forceinline__ float funmap(unsigned m) {
    return (m & 0x80000000u) ? __uint_as_float(m ^ 0x80000000u)
                             : __uint_as_float(~m);
}
__device__ __forceinline__ float tanh_hw(float v) {
    float r;
    asm("tanh.approx.f32 %0, %1;" : "=f"(r) : "f"(v));
    return r;
}
__device__ __forceinline__ void cp16(unsigned saddr, const void* g) {
    asm volatile("cp.async.cg.shared.global [%0], [%1], 16;\n"
                 :: "r"(saddr), "l"(g) : "memory");
}
__device__ __forceinline__ void cp_commit() {
    asm volatile("cp.async.commit_group;\n" ::: "memory");
}
__device__ __forceinline__ void cp_wait0() {
    asm volatile("cp.async.wait_group 0;\n" ::: "memory");
}
__device__ __forceinline__ void ldsm4(unsigned r[4], unsigned saddr) {
    asm volatile("ldmatrix.sync.aligned.m8n8.x4.shared.b16 {%0,%1,%2,%3}, [%4];\n"
                 : "=r"(r[0]), "=r"(r[1]), "=r"(r[2]), "=r"(r[3]) : "r"(saddr));
}
__device__ __forceinline__ void mma16816(float c[4], const unsigned a[4],
                                         unsigned b0, unsigned b1) {
    asm volatile(
        "mma.sync.aligned.m16n8k16.row.col.f32.f16.f16.f32 "
        "{%0,%1,%2,%3}, {%4,%5,%6,%7}, {%8,%9}, {%0,%1,%2,%3};\n"
        : "+f"(c[0]), "+f"(c[1]), "+f"(c[2]), "+f"(c[3])
        : "r"(a[0]), "r"(a[1]), "r"(a[2]), "r"(a[3]), "r"(b0), "r"(b1));
}

// ---------------------------------------------------------------------------
// k0: zero out + seg scratch; detect idx dtype; pack W1^T as half (n-major).
// ---------------------------------------------------------------------------
__global__ void k0_init(float* __restrict__ out, const void* __restrict__ idxp,
                        const float* __restrict__ W1) {
    long long i = (long long)blockIdx.x * blockDim.x + threadIdx.x;
    if (i < NSEG * D) out[i] = 0.0f;
    if (i < NSEG) { g_segsum[i] = 0.0f; g_segmaxb[i] = 0u; }
    if (i < D * D) {
        int n = (int)(i / D), k = (int)(i % D);
        g_w1h[i] = __float2half_rn(W1[(size_t)k * D + n]);
    }
    if (i == 0) {
        const long long* p64 = (const long long*)idxp;
        long long a = p64[NROWS / 4];
        long long b = p64[NROWS / 8];
        g_is64 = (a >= 0 && a < NSEG && b >= 0 && b < NSEG) ? 1 : 0;
    }
}

// ---------------------------------------------------------------------------
// k1: persistent fp16-mma MLP. 512 threads, 16 warps (warp tile m32 x n32).
// LDG.128 prefetch -> register convert -> STS.64. Direct global atomicMax
// (fire-and-forget) for segment max -- no serial run scan, 2 barriers/tile.
// ---------------------------------------------------------------------------
__global__ __launch_bounds__(512, 1)
void k1_mlp(const float* __restrict__ x,
            const float* __restrict__ b1, const float* __restrict__ W2,
            const float* __restrict__ b2, const void* __restrict__ idxp)
{
    extern __shared__ char sm[];
    float2* bwp  = (float2*)(sm + MISC_OFF);
    float*  sred = (float*)(sm + MISC_OFF + 1024);

    const unsigned s_base  = (unsigned)__cvta_generic_to_shared(sm);
    const unsigned s_ws    = s_base + WS_OFF;
    const unsigned s_xh[2] = { s_base + XH0_OFF, s_base + XH1_OFF };

    const int tid  = threadIdx.x;
    const int lane = tid & 31;
    const int warp = tid >> 5;
    const int gid  = lane >> 2;
    const int tig  = lane & 3;
    const int m0   = (warp & 3) * 32;
    const int n0   = (warp >> 2) * 32;
    const int grid = gridDim.x;
    const int cta  = blockIdx.x;
    const int n_t  = (NTILES - cta + grid - 1) / grid;
    const int is64 = g_is64;

    const int cv_r0 = tid >> 5;
    const int cv_cc = tid & 31;

    const unsigned a_off = (unsigned)((m0 + (lane & 15)) * (WSTR * 2) + ((lane >> 4) * 16));
    const unsigned b_off = (unsigned)((n0 + (lane & 7) + ((lane >> 4) << 3)) * (WSTR * 2)
                                      + (((lane >> 3) & 1) * 16));

    if (tid < 128) {
        bwp[tid] = make_float2(b1[tid], W2[tid]);
        sred[tid] = 0.0f;
    }
    const float b2v = b2[0];

    if (n_t == 0) return;

    // ---- prologue: ws via cp.async (one-time), tile0 via LDG->cvt->STS ----
#pragma unroll
    for (int c = 0; c < 4; c++) {
        int q = tid + c * 512;
        int r = q >> 4, cc = q & 15;
        cp16(s_ws + (unsigned)(r * (WSTR * 2) + cc * 16),
             g_w1h + (size_t)r * D + cc * 8);
    }
    cp_commit();
    {
        const float4* xb = (const float4*)(x + (size_t)cta * 128 * D);
        float4 rv[8];
#pragma unroll
        for (int j = 0; j < 8; j++) rv[j] = xb[tid + j * 512];
        cp_wait0();
        __syncthreads();   // ws ready; also orders smem init
#pragma unroll
        for (int j = 0; j < 8; j++) {
            __half2 h0 = __floats2half2_rn(rv[j].x, rv[j].y);
            __half2 h1 = __floats2half2_rn(rv[j].z, rv[j].w);
            uint2 u = { *(unsigned*)&h0, *(unsigned*)&h1 };
            *(uint2*)(sm + XH0_OFF + (size_t)(cv_r0 + 16 * j) * (WSTR * 2) + cv_cc * 8) = u;
        }
        __syncthreads();
    }

    for (int i = 0; i < n_t; i++) {
        const int b = i & 1;
        const unsigned xa = s_xh[b] + a_off;
        const unsigned bb = s_ws + b_off;
        const bool have_next = (i + 1 < n_t);
        const size_t row0 = ((size_t)cta + (size_t)i * grid) * 128;

        // ---- prefetch tile i+1 x-data and tile i idx (latency hides under MMA) ----
        float4 rv[8];
        if (have_next) {
            const float4* xn = (const float4*)(x + ((size_t)cta + (size_t)(i + 1) * grid) * 128 * D);
#pragma unroll
            for (int j = 0; j < 8; j++) rv[j] = xn[tid + j * 512];
        }
        int myseg = 0;
        if (tid < 128) myseg = seg_at(idxp, is64, (long long)(row0 + tid));

        // ---- mainloop: 8 k16 steps, warp tile m32 x n32 ----
        float c[2][4][4];
#pragma unroll
        for (int mi = 0; mi < 2; mi++)
#pragma unroll
            for (int nj = 0; nj < 4; nj++)
#pragma unroll
                for (int r = 0; r < 4; r++) c[mi][nj][r] = 0.0f;

#pragma unroll
        for (int k0 = 0; k0 < 8; k0++) {
            unsigned af[2][4], bf[2][4];
            ldsm4(af[0], xa + k0 * 32);
            ldsm4(af[1], xa + 16 * (WSTR * 2) + k0 * 32);
            ldsm4(bf[0], bb + k0 * 32);
            ldsm4(bf[1], bb + 16 * (WSTR * 2) + k0 * 32);
#pragma unroll
            for (int mi = 0; mi < 2; mi++)
#pragma unroll
                for (int nj2 = 0; nj2 < 2; nj2++) {
                    mma16816(c[mi][nj2 * 2],     af[mi], bf[nj2][0], bf[nj2][1]);
                    mma16816(c[mi][nj2 * 2 + 1], af[mi], bf[nj2][2], bf[nj2][3]);
                }
        }

        __syncthreads();   // everyone done reading xh[b^1] from prior iter

        // ---- store tile i+1 into xh[b^1] ----
        if (have_next) {
            char* dst = sm + (b ? XH0_OFF : XH1_OFF);
#pragma unroll
            for (int j = 0; j < 8; j++) {
                __half2 h0 = __floats2half2_rn(rv[j].x, rv[j].y);
                __half2 h1 = __floats2half2_rn(rv[j].z, rv[j].w);
                uint2 u = { *(unsigned*)&h0, *(unsigned*)&h1 };
                *(uint2*)(dst + (size_t)(cv_r0 + 16 * j) * (WSTR * 2) + cv_cc * 8) = u;
            }
        }

        // ---- epilogue: bias + hw-tanh + dot(W2) -> per-row score ----
        float b1v[4][2], w2v[4][2];
#pragma unroll
        for (int nj = 0; nj < 4; nj++)
#pragma unroll
            for (int cc = 0; cc < 2; cc++) {
                float2 bw = bwp[n0 + nj * 8 + tig * 2 + cc];
                b1v[nj][cc] = bw.x;
                w2v[nj][cc] = bw.y;
            }
        float rp[4] = {0.0f, 0.0f, 0.0f, 0.0f};
#pragma unroll
        for (int mi = 0; mi < 2; mi++)
#pragma unroll
            for (int nj = 0; nj < 4; nj++)
#pragma unroll
                for (int r = 0; r < 4; r++) {
                    float h = tanh_hw(c[mi][nj][r] + b1v[nj][r & 1]);
                    rp[mi * 2 + (r >> 1)] = fmaf(h, w2v[nj][r & 1], rp[mi * 2 + (r >> 1)]);
                }
#pragma unroll
        for (int q = 0; q < 4; q++) {
            rp[q] += __shfl_xor_sync(0xffffffffu, rp[q], 1);
            rp[q] += __shfl_xor_sync(0xffffffffu, rp[q], 2);
        }
        if (tig == 0) {
#pragma unroll
            for (int q = 0; q < 4; q++) {
                int row = m0 + (q >> 1) * 16 + (q & 1) * 8 + gid;
                atomicAdd(&sred[row], rp[q]);
            }
        }
        __syncthreads();   // sred complete + xh[b^1] stored

        // ---- score out: direct fire-and-forget segment atomicMax ----
        if (tid < 128) {
            float sv = sred[tid] + b2v;
            g_s[row0 + tid] = sv;
            atomicMax(&g_segmaxb[myseg], fmap(sv));
            sred[tid] = 0.0f;   // ordered before next tile's adds by next sync
        }
    }
}

// ---------------------------------------------------------------------------
// k2: e = exp(s - seg_max[idx]); smem bucket aggregation of seg_sum.
// ---------------------------------------------------------------------------
__global__ __launch_bounds__(256) void k2_exp(
    const void* __restrict__ idxp, float* __restrict__ e_out)
{
    __shared__ float buck[1024];
    const int tid = threadIdx.x;
    const long long base = (long long)blockIdx.x * 1024;
    const long long last = min(base + 1023LL, (long long)NROWS - 1);
    const int is64 = g_is64;
    const int seg_lo = seg_at(idxp, is64, base);
    const int seg_hi = seg_at(idxp, is64, last);
    const int range = seg_hi - seg_lo + 1;
    const bool use_smem = (range > 0 && range <= 1024);
    if (use_smem)
        for (int k = tid; k < range; k += 256) buck[k] = 0.0f;
    __syncthreads();

    for (int j = tid; j < 1024; j += 256) {
        long long r = base + j;
        if (r >= NROWS) break;
        int seg = seg_at(idxp, is64, r);
        float smax = funmap(g_segmaxb[seg]);
        float e = __expf(g_s[r] - smax);
        e_out[r] = e;
        if (use_smem) atomicAdd(&buck[seg - seg_lo], e);
        else          atomicAdd(&g_segsum[seg], e);
    }
    __syncthreads();

    if (use_smem)
        for (int k = tid; k < range; k += 256) {
            float v = buck[k];
            if (v != 0.0f) atomicAdd(&g_segsum[seg_lo + k], v);
        }
}

// ---------------------------------------------------------------------------
// k3: alpha = e/(seg_sum+1e-16); out += x*alpha with register accumulation.
// ---------------------------------------------------------------------------
__global__ __launch_bounds__(128) void k3_agg(
    const float* __restrict__ x, const void* __restrict__ idxp,
    float* __restrict__ alpha, float* __restrict__ out)
{
    __shared__ float sa[512];
    __shared__ int   sseg[512];
    const int tid = threadIdx.x;
    const long long base = (long long)blockIdx.x * 512;
    const int nrows = (int)min(512LL, (long long)NROWS - base);
    const int is64 = g_is64;

    for (int j = tid; j < nrows; j += 128) {
        int seg = seg_at(idxp, is64, base + j);
        float e = alpha[base + j];
        float a = __fdividef(e, g_segsum[seg] + 1e-16f);
        sa[j] = a;
        sseg[j] = seg;
        alpha[base + j] = a;
    }
    __syncthreads();

    float acc = 0.0f;
    int cur = sseg[0];
    for (int j = 0; j < nrows; j++) {
        int sg = sseg[j];
        if (sg != cur) {
            atomicAdd(&out[(size_t)cur * D + tid], acc);
            acc = 0.0f;
            cur = sg;
        }
        acc = fmaf(x[(size_t)(base + j) * D + tid], sa[j], acc);
    }
    atomicAdd(&out[(size_t)cur * D + tid], acc);
}

// ---------------------------------------------------------------------------
extern "C" void kernel_launch(void* const* d_in, const int* in_sizes, int n_in,
                              void* d_out, int out_size)
{
    const float* x  = (const float*)d_in[0];
    const float* W1 = (const float*)d_in[1];
    const float* b1 = (const float*)d_in[2];
    const float* W2 = (const float*)d_in[3];
    const float* b2 = (const float*)d_in[4];
    const void*  idxp = d_in[5];

    float* outp  = (float*)d_out;          // (4096, 128)
    float* alpha = outp + NSEG * D;        // (N, 1) -- holds e between k2/k3

    static int sms = 0;
    if (!sms) {
        cudaDeviceGetAttribute(&sms, cudaDevAttrMultiProcessorCount, 0);
        cudaFuncSetAttribute(k1_mlp, cudaFuncAttributeMaxDynamicSharedMemorySize,
                             SMEM_TOTAL);
    }

    k0_init<<<(NSEG * D + 255) / 256, 256>>>(outp, idxp, W1);
    k1_mlp <<<sms, 512, SMEM_TOTAL>>>(x, b1, W2, b2, idxp);
    k2_exp <<<(NROWS + 1023) / 1024, 256>>>(idxp, alpha);
    k3_agg <<<(NROWS + 511) / 512, 128>>>(x, idxp, alpha, outp);
}